// round 13
// baseline (speedup 1.0000x reference)
#include <cuda_runtime.h>
#include <cuda_bf16.h>
#include <cuda_fp16.h>
#include <cstdint>

#define FULL_MASK 0xFFFFFFFFu

// ------------------------- device scratch ----------------------------------
__device__ float g_u[512 * 4];
__device__ float g_c1[4];
__device__ float g_dpart[2048 * 4];
__device__ float g_spart[1024 * 2048];
__device__ float g_spart2[16 * 2048];
__device__ float g_x1[512];
__device__ float g_x2[512];
__device__ float g_qk[1024];
__device__ float g_U[512 * 4];
__device__ float g_c[4];
__device__ float g_vals[512];
__device__ float g_sv[4];
__device__ float g_svv[4];
// Wm^T in fp16, chunk-major: [kchunk64][n][kk] with kchunk64 = k/64, kk = k%64
__device__ __half g_WmB[512 * 512];

// ------------------------- helpers -----------------------------------------
__device__ __forceinline__ unsigned long long pack2(float lo, float hi) {
    unsigned long long r;
    asm("mov.b64 %0, {%1, %2};" : "=l"(r) : "f"(lo), "f"(hi));
    return r;
}
__device__ __forceinline__ void unpack2(unsigned long long v, float& lo, float& hi) {
    asm("mov.b64 {%0, %1}, %2;" : "=f"(lo), "=f"(hi) : "l"(v));
}
__device__ __forceinline__ void fma2(unsigned long long& acc,
                                     unsigned long long a, unsigned long long b) {
    asm("fma.rn.f32x2 %0, %1, %2, %0;" : "+l"(acc) : "l"(a), "l"(b));
}
__device__ __forceinline__ float silu_fast(float x) {
    return __fdividef(x, 1.0f + __expf(-x));
}
__device__ __forceinline__ uint32_t smem_u32(const void* p) {
    uint32_t a;
    asm("{ .reg .u64 t; cvta.to.shared.u64 t, %1; cvt.u32.u64 %0, t; }" : "=r"(a) : "l"(p));
    return a;
}
__device__ __forceinline__ uint32_t pkh(__half a, __half b) {
    return (uint32_t)__half_as_ushort(a) | ((uint32_t)__half_as_ushort(b) << 16);
}
__device__ __forceinline__ void cp16(uint32_t dst, const void* src) {
    asm volatile("cp.async.cg.shared.global [%0], [%1], 16;" :: "r"(dst), "l"(src));
}
__device__ __forceinline__ void ldsm4(uint32_t& r0, uint32_t& r1, uint32_t& r2,
                                      uint32_t& r3, uint32_t addr) {
    asm volatile("ldmatrix.sync.aligned.m8n8.x4.shared.b16 {%0,%1,%2,%3}, [%4];"
                 : "=r"(r0), "=r"(r1), "=r"(r2), "=r"(r3) : "r"(addr));
}
__device__ __forceinline__ void mma_f16(float& d0, float& d1, float& d2, float& d3,
                                        uint32_t a0, uint32_t a1, uint32_t a2, uint32_t a3,
                                        uint32_t b0, uint32_t b1) {
    asm volatile(
        "mma.sync.aligned.m16n8k16.row.col.f32.f16.f16.f32 "
        "{%0,%1,%2,%3}, {%4,%5,%6,%7}, {%8,%9}, {%0,%1,%2,%3};"
        : "+f"(d0), "+f"(d1), "+f"(d2), "+f"(d3)
        : "r"(a0), "r"(a1), "r"(a2), "r"(a3), "r"(b0), "r"(b1));
}

// ------------------------- kernel: prep fused (Wm fp16 + Wq/rk fold) --------
__global__ void __launch_bounds__(1024) k_prepF(const float* __restrict__ Wm,
                                                const float* __restrict__ Wq,
                                                const float* __restrict__ bq,
                                                const float* __restrict__ rk) {
    if (blockIdx.x == 16) {
        if (blockIdx.y == 0) {
            int t = threadIdx.y * 32 + threadIdx.x;
            if (t < 512) {
                float u[4];
#pragma unroll
                for (int r = 0; r < 4; r++) {
                    float s = 0.f;
#pragma unroll
                    for (int d = 0; d < 4; d++) s += Wq[t * 16 + 4 * r + d] * rk[4 * r + d];
                    u[r] = s;
                }
                ((float4*)g_u)[t] = make_float4(u[0], u[1], u[2], u[3]);
                if (t < 4) {
                    float s = 0.f;
#pragma unroll
                    for (int d = 0; d < 4; d++) s += bq[4 * t + d] * rk[4 * t + d];
                    g_c1[t] = s;
                }
            }
        }
        return;
    }
    __shared__ float tile[32][33];
    int tx = threadIdx.x, ty = threadIdx.y;
    tile[ty][tx] = Wm[(blockIdx.y * 32 + ty) * 512 + blockIdx.x * 32 + tx];
    __syncthreads();
    int n = blockIdx.x * 32 + ty;
    int k = blockIdx.y * 32 + tx;
    float v = tile[tx][ty];
    size_t idx = ((size_t)(k >> 6) * 512 + n) * 64 + (k & 63);
    g_WmB[idx] = __float2half(v);
}

// ------------------------- kernel: fused pass 1 -----------------------------
__global__ void __launch_bounds__(512) k_pass1(const float* __restrict__ h, int n) {
    __shared__ float4 se[128];
    __shared__ float sD[16][4];
    const int tid = threadIdx.x, warp = tid >> 5, lane = tid & 31;
    const int base = blockIdx.x * 128;

    const float c10 = g_c1[0], c11 = g_c1[1], c12 = g_c1[2], c13 = g_c1[3];
    float d0 = 0.f, d1 = 0.f, d2 = 0.f, d3 = 0.f;

#pragma unroll
    for (int rr = 0; rr < 8; rr++) {
        const int rloc = warp * 8 + rr;
        const int row = base + rloc;
        const bool valid = (row < n);
        const float* hr = h + (size_t)row * 512;

        float l0 = 0.f, l1 = 0.f, l2 = 0.f, l3 = 0.f;
        if (valid) {
#pragma unroll
            for (int t = 0; t < 16; t++) {
                int k = lane + 32 * t;
                float hk = __ldg(hr + k);
                float4 u = __ldg((const float4*)g_u + k);
                l0 += hk * u.x; l1 += hk * u.y; l2 += hk * u.z; l3 += hk * u.w;
            }
        }
#pragma unroll
        for (int o = 16; o; o >>= 1) {
            l0 += __shfl_xor_sync(FULL_MASK, l0, o);
            l1 += __shfl_xor_sync(FULL_MASK, l1, o);
            l2 += __shfl_xor_sync(FULL_MASK, l2, o);
            l3 += __shfl_xor_sync(FULL_MASK, l3, o);
        }
        if (lane == 0) {
            float m = valid ? 1.f : 0.f;
            float e0 = m * __expf(0.5f * (l0 + c10));
            float e1 = m * __expf(0.5f * (l1 + c11));
            float e2 = m * __expf(0.5f * (l2 + c12));
            float e3 = m * __expf(0.5f * (l3 + c13));
            se[rloc] = make_float4(e0, e1, e2, e3);
            d0 += e0; d1 += e1; d2 += e2; d3 += e3;
        }
    }
    if (lane == 0) {
        sD[warp][0] = d0; sD[warp][1] = d1; sD[warp][2] = d2; sD[warp][3] = d3;
    }
    __syncthreads();
    if (warp == 0 && lane < 4) {
        float s = 0.f;
#pragma unroll
        for (int w = 0; w < 16; w++) s += sD[w][lane];
        g_dpart[blockIdx.x * 4 + lane] = s;
    }

    const int c = tid;
    int lim = n - base; if (lim > 128) lim = 128;
    unsigned long long a01 = pack2(0.f, 0.f), a23 = pack2(0.f, 0.f);
    const float* hc = h + (size_t)base * 512 + c;
#pragma unroll 4
    for (int i = 0; i < lim; i++) {
        float4 e = se[i];
        float hv = __ldg(hc + (size_t)i * 512);
        unsigned long long hd = pack2(hv, hv);
        fma2(a01, hd, pack2(e.x, e.y));
        fma2(a23, hd, pack2(e.z, e.w));
    }
    float s0, s1, s2, s3;
    unpack2(a01, s0, s1);
    unpack2(a23, s2, s3);
    float* dst = g_spart + (size_t)blockIdx.x * 2048;
    dst[0 * 512 + c] = s0;
    dst[1 * 512 + c] = s1;
    dst[2 * 512 + c] = s2;
    dst[3 * 512 + c] = s3;
}

// ------------------------- kernel: S partial reduction (grid 4x16) ----------
__global__ void __launch_bounds__(512) k_redS(int nb) {
    const int col = blockIdx.x * 512 + threadIdx.x;
    const int chunk = (nb + 15) / 16;
    int i0 = blockIdx.y * chunk;
    int i1 = i0 + chunk; if (i1 > nb) i1 = nb;
    float s = 0.f;
    const float* src = g_spart + col;
#pragma unroll 4
    for (int i = i0; i < i1; i++) s += src[(size_t)i * 2048];
    g_spart2[blockIdx.y * 2048 + col] = s;
}

// ------------------------- kernel: smallA (S/D finalize, LN chain, x1) ------
__global__ void __launch_bounds__(512) k_smallA(int nb,
        const float* __restrict__ Wv,  const float* __restrict__ bv,
        const float* __restrict__ lrs, const float* __restrict__ lrb,
        const float* __restrict__ l1s, const float* __restrict__ l1b,
        const float* __restrict__ W1,  const float* __restrict__ b1) {
    __shared__ float sS[4 * 512];
    __shared__ float sDv[4];
    __shared__ float sNum[16];
    __shared__ float sr16[16];
    const int tid = threadIdx.x, warp = tid >> 5, lane = tid & 31;

#pragma unroll
    for (int r = 0; r < 4; r++) {
        int col = r * 512 + tid;
        float s = 0.f;
#pragma unroll
        for (int j = 0; j < 16; j++) s += g_spart2[j * 2048 + col];
        sS[col] = s;
    }
    if (warp < 4) {
        float s = 0.f;
        for (int i = lane; i < nb; i += 32) s += g_dpart[i * 4 + warp];
#pragma unroll
        for (int o = 16; o; o >>= 1) s += __shfl_xor_sync(FULL_MASK, s, o);
        if (lane == 0) sDv[warp] = s;
    }
    __syncthreads();

    {
        const int r = warp >> 2;
        float s = 0.f;
        for (int c = lane; c < 512; c += 32) s += sS[r * 512 + c] * Wv[c * 16 + warp];
#pragma unroll
        for (int o = 16; o; o >>= 1) s += __shfl_xor_sync(FULL_MASK, s, o);
        if (lane == 0) sNum[warp] = s;
    }
    __syncthreads();

    if (tid == 0) {
        float reg[16];
#pragma unroll
        for (int i = 0; i < 16; i++) reg[i] = sNum[i] / sDv[i >> 2] + bv[i];
#pragma unroll
        for (int pass = 0; pass < 2; pass++) {
            const float* sc = pass ? l1s : lrs;
            const float* bc = pass ? l1b : lrb;
            float m = 0.f;
            for (int i = 0; i < 16; i++) m += reg[i];
            m *= (1.f / 16.f);
            float v = 0.f;
            for (int i = 0; i < 16; i++) { float d = reg[i] - m; v += d * d; }
            v *= (1.f / 16.f);
            float inv = rsqrtf(v + 1e-6f);
            for (int i = 0; i < 16; i++) reg[i] = (reg[i] - m) * inv * sc[i] + bc[i];
        }
        for (int i = 0; i < 16; i++) sr16[i] = reg[i];
    }
    __syncthreads();

    float s = b1[tid];
#pragma unroll
    for (int i = 0; i < 16; i++) s += sr16[i] * W1[i * 512 + tid];
    g_x1[tid] = s / (1.f + expf(-s));
}

// ------------------------- kernel: smallB2 — x2 (grid 8) --------------------
__global__ void __launch_bounds__(512) k_smallB2(const float* __restrict__ W2,
                                                 const float* __restrict__ b2) {
    __shared__ float sx1[512];
    __shared__ float red[512];
    const int t = threadIdx.x;
    sx1[t] = g_x1[t];
    __syncthreads();
    const int j = blockIdx.x * 64 + (t & 63);
    const int ks = t >> 6;   // 8 k-slices of 64
    float s = 0.f;
    const float* w = W2 + (size_t)(ks * 64) * 512 + j;
    const float* xs = sx1 + ks * 64;
#pragma unroll 16
    for (int k = 0; k < 64; k++) s += xs[k] * __ldg(w + (size_t)k * 512);
    red[t] = s;
    __syncthreads();
    if (t < 64) {
        float v = b2[blockIdx.x * 64 + t];
#pragma unroll
        for (int i = 0; i < 8; i++) v += red[i * 64 + t];
        g_x2[blockIdx.x * 64 + t] = v / (1.f + expf(-v));
    }
}

// ------------------------- kernel: smallC2 — qk (grid 16) -------------------
__global__ void __launch_bounds__(512) k_smallC2(const float* __restrict__ W3,
                                                 const float* __restrict__ b3) {
    __shared__ float sx2[512];
    __shared__ float red[512];
    const int t = threadIdx.x;
    sx2[t] = g_x2[t];
    __syncthreads();
    const int j = blockIdx.x * 64 + (t & 63);
    const int ks = t >> 6;
    float s = 0.f;
    const float* w = W3 + (size_t)(ks * 64) * 1024 + j;
    const float* xs = sx2 + ks * 64;
#pragma unroll 16
    for (int k = 0; k < 64; k++) s += xs[k] * __ldg(w + (size_t)k * 1024);
    red[t] = s;
    __syncthreads();
    if (t < 64) {
        float v = b3[blockIdx.x * 64 + t];
#pragma unroll
        for (int i = 0; i < 8; i++) v += red[i * 64 + t];
        g_qk[blockIdx.x * 64 + t] = v;
    }
}

// ------------------------- kernel: smallD2 — U fold + stats (grid 9) --------
__global__ void __launch_bounds__(512) k_smallD2(const float* __restrict__ Wk,
                                                 const float* __restrict__ bk) {
    const int t = threadIdx.x, warp = t >> 5, lane = t & 31;
    if (blockIdx.x == 8) {
        g_vals[t] = g_qk[512 + t];
        if (warp < 4) {
            float s = 0.f, sv = 0.f, svv = 0.f;
            for (int d = lane; d < 128; d += 32) {
                float qv = g_qk[warp * 128 + d];
                s += bk[warp * 128 + d] * qv;
                float v = g_qk[512 + warp * 128 + d];
                sv += v; svv += v * v;
            }
#pragma unroll
            for (int o = 16; o; o >>= 1) {
                s   += __shfl_xor_sync(FULL_MASK, s, o);
                sv  += __shfl_xor_sync(FULL_MASK, sv, o);
                svv += __shfl_xor_sync(FULL_MASK, svv, o);
            }
            if (lane == 0) {
                g_c[warp] = s * rsqrtf(128.f);
                g_sv[warp] = sv;
                g_svv[warp] = svv;
            }
        }
        return;
    }
    __shared__ float sqk[1024];
    __shared__ float red[512];
    sqk[t] = g_qk[t];
    sqk[t + 512] = g_qk[t + 512];
    __syncthreads();
    const int r = blockIdx.x * 64 + (t >> 3);
    const int p = t & 7, head = p >> 1, half = p & 1;
    const float4* wr = (const float4*)(Wk + (size_t)r * 512 + head * 128 + half * 64);
    const float* qv = sqk + head * 128 + half * 64;
    float s = 0.f;
#pragma unroll
    for (int d4 = 0; d4 < 16; d4++) {
        float4 w = __ldg(wr + d4);
        s += w.x * qv[4 * d4 + 0] + w.y * qv[4 * d4 + 1]
           + w.z * qv[4 * d4 + 2] + w.w * qv[4 * d4 + 3];
    }
    red[t] = s;
    __syncthreads();
    if (t < 256) {
        const int rr = t >> 2, hh = t & 3;
        float v = red[rr * 8 + hh * 2] + red[rr * 8 + hh * 2 + 1];
        g_U[(blockIdx.x * 64 + rr) * 4 + hh] = v * rsqrtf(128.f);
    }
}

// ------------------------- kernel: main (HMMA fp16, Kc=64 chunks) -----------
// Block: 64 rows x 512 cols, 512 threads (16 warps, warp tile 32x64).
// K chunked at 64, double buffered; B fp16 via cp.async(16B), A fp16 built
// in-kernel with LN2. 1 MMA pass.
#define BSTRIDE 144
#define B_BUF_STRIDE 73728
#define OFF_A 147456
#define A_BUF_STRIDE 9216
#define OFF_SA 165888
#define OFF_MEAN 166912
#define OFF_INV 167168
#define SMEM_DYN 167424

__device__ __forceinline__ void loadB_async(uint32_t base32, int buf, int kc, int tid) {
    const __half* sH = g_WmB + (size_t)kc * 32768;
    uint32_t bh = base32 + buf * B_BUF_STRIDE;
#pragma unroll
    for (int j = 0; j < 8; j++) {
        int f = j * 512 + tid;   // 16B-unit index; 8 units per 128B row
        uint32_t doff = (uint32_t)((f >> 3) * BSTRIDE + (f & 7) * 16);
        cp16(bh + doff, sH + f * 8);
    }
}

// Build 8 contiguous k values (k = kc*64 + kq*8 .. +7) of row arow.
__device__ __forceinline__ void build_a_sts(char* sb, int buf, int kc, int arow, int kq,
        float4 hv0, float4 hv1, bool valid, const float* sa, const float* smean,
        const float* sinv, const float* __restrict__ ln2s, const float* __restrict__ ln2b) {
    const int kg = kc * 64 + kq * 8;
    const float ah = sa[arow * 4 + (kc >> 1)];
    const float mean = smean[arow], inv = sinv[arow];
    float4 vA = __ldg((const float4*)(g_vals + kg));
    float4 vB = __ldg((const float4*)(g_vals + kg + 4));
    float4 sA = __ldg((const float4*)(ln2s + kg));
    float4 sB = __ldg((const float4*)(ln2s + kg + 4));
    float4 bA = __ldg((const float4*)(ln2b + kg));
    float4 bB = __ldg((const float4*)(ln2b + kg + 4));
    float hx[8] = {hv0.x, hv0.y, hv0.z, hv0.w, hv1.x, hv1.y, hv1.z, hv1.w};
    float vx[8] = {vA.x, vA.y, vA.z, vA.w, vB.x, vB.y, vB.z, vB.w};
    float sx[8] = {sA.x, sA.y, sA.z, sA.w, sB.x, sB.y, sB.z, sB.w};
    float bx[8] = {bA.x, bA.y, bA.z, bA.w, bB.x, bB.y, bB.z, bB.w};
    uint32_t w[4];
#pragma unroll
    for (int p = 0; p < 4; p++) {
        __half h0, h1;
        float x0 = valid ? ((hx[2 * p] + ah * vx[2 * p] - mean) * inv * sx[2 * p] + bx[2 * p]) : 0.f;
        float x1 = valid ? ((hx[2 * p + 1] + ah * vx[2 * p + 1] - mean) * inv * sx[2 * p + 1] + bx[2 * p + 1]) : 0.f;
        h0 = __float2half(x0);
        h1 = __float2half(x1);
        w[p] = pkh(h0, h1);
    }
    char* dst = sb + OFF_A + buf * A_BUF_STRIDE + arow * BSTRIDE + kq * 16;
    *(uint4*)dst = make_uint4(w[0], w[1], w[2], w[3]);
}

__global__ void __launch_bounds__(512, 1) k_main_mma(const float* __restrict__ h,
        const float* __restrict__ ln2s, const float* __restrict__ ln2b,
        const float* __restrict__ bm,
        const float* __restrict__ ln3s, const float* __restrict__ ln3b,
        float* __restrict__ out, int n) {
    extern __shared__ char sb[];
    const uint32_t base32 = smem_u32(sb);
    float* sa    = (float*)(sb + OFF_SA);
    float* smean = (float*)(sb + OFF_MEAN);
    float* sinv  = (float*)(sb + OFF_INV);
    float* sd    = (float*)sb;

    const int tid = threadIdx.x, warp = tid >> 5, lane = tid & 31;
    const int row0 = blockIdx.x * 64;

    // ---------- Phase A: per-row softmax + closed-form LN2 stats ------------
    {
        const float c0 = g_c[0], c1 = g_c[1], c2 = g_c[2], c3 = g_c[3];
        const float sv0 = g_sv[0], sv1 = g_sv[1], sv2 = g_sv[2], sv3 = g_sv[3];
        const float w0 = g_svv[0], w1 = g_svv[1], w2 = g_svv[2], w3 = g_svv[3];
#pragma unroll
        for (int rr = 0; rr < 4; rr++) {
            const int rloc = warp * 4 + rr;
            const int row = row0 + rloc;
            const bool valid = (row < n);
            const float* hr = h + (size_t)row * 512;
            float l0 = 0.f, l1 = 0.f, l2 = 0.f, l3 = 0.f;
            float hv0 = 0.f, hv1 = 0.f, hv2 = 0.f, hv3 = 0.f;
            float sh = 0.f, sq = 0.f;
            if (valid) {
#pragma unroll
                for (int t = 0; t < 16; t++) {
                    int k = lane + 32 * t;
                    float hk = __ldg(hr + k);
                    float4 u = __ldg((const float4*)g_U + k);
                    float vk = __ldg(g_vals + k);
                    l0 += hk * u.x; l1 += hk * u.y; l2 += hk * u.z; l3 += hk * u.w;
                    float p = hk * vk;
                    if (t < 4) hv0 += p; else if (t < 8) hv1 += p;
                    else if (t < 12) hv2 += p; else hv3 += p;
                    sh += hk; sq += hk * hk;
                }
            }
#pragma unroll
            for (int o = 16; o; o >>= 1) {
                l0 += __shfl_xor_sync(FULL_MASK, l0, o);
                l1 += __shfl_xor_sync(FULL_MASK, l1, o);
                l2 += __shfl_xor_sync(FULL_MASK, l2, o);
                l3 += __shfl_xor_sync(FULL_MASK, l3, o);
                hv0 += __shfl_xor_sync(FULL_MASK, hv0, o);
                hv1 += __shfl_xor_sync(FULL_MASK, hv1, o);
                hv2 += __shfl_xor_sync(FULL_MASK, hv2, o);
                hv3 += __shfl_xor_sync(FULL_MASK, hv3, o);
                sh += __shfl_xor_sync(FULL_MASK, sh, o);
                sq += __shfl_xor_sync(FULL_MASK, sq, o);
            }
            if (lane == 0) {
                if (valid) {
                    l0 += c0; l1 += c1; l2 += c2; l3 += c3;
                    float mx = fmaxf(fmaxf(l0, l1), fmaxf(l2, l3));
                    float e0 = __expf(l0 - mx), e1 = __expf(l1 - mx);
                    float e2 = __expf(l2 - mx), e3 = __expf(l3 - mx);
                    float si = __fdividef(1.f, e0 + e1 + e2 + e3);
                    float a0 = e0 * si, a1 = e1 * si, a2 = e2 * si, a3 = e3 * si;
                    float sum = sh + a0 * sv0 + a1 * sv1 + a2 * sv2 + a3 * sv3;
                    float ssq = sq + 2.f * (a0 * hv0 + a1 * hv1 + a2 * hv2 + a3 * hv3)
                              + a0 * a0 * w0 + a1 * a1 * w1 + a2 * a2 * w2 + a3 * a3 * w3;
                    float mean = sum * (1.f / 512.f);
                    float var = ssq * (1.f / 512.f) - mean * mean;
                    sa[rloc * 4 + 0] = a0; sa[rloc * 4 + 1] = a1;
                    sa[rloc * 4 + 2] = a2; sa[rloc * 4 + 3] = a3;
                    smean[rloc] = mean;
                    sinv[rloc] = rsqrtf(var + 1e-6f);
                } else {
                    sa[rloc * 4 + 0] = 0.f; sa[rloc * 4 + 1] = 0.f;
                    sa[rloc * 4 + 2] = 0.f; sa[rloc * 4 + 3] = 0.f;
                    smean[rloc] = 0.f; sinv[rloc] = 0.f;
                }
            }
        }
    }
    __syncthreads();

    // ---------- GEMM pipeline (8 chunks of Kc=64) ----------------------------
    const int arow = tid >> 3, kq = tid & 7;
    const bool avalid = (row0 + arow < n);
    const float* harow = h + (size_t)(row0 + arow) * 512;
    const int rowg = warp >> 3, colg = warp & 7;
    const int g = lane >> 2, tig = lane & 3;

    const uint32_t aoff = (uint32_t)((lane & 15) * BSTRIDE + (lane >> 4) * 16);
    const uint32_t boff = (uint32_t)(((((lane >> 4) << 3) + (lane & 7)) * BSTRIDE)
                                     + ((lane >> 3) & 1) * 16);
    const uint32_t aAddr = base32 + OFF_A + (uint32_t)(rowg * 32) * BSTRIDE + aoff;
    const uint32_t bAddr = base32 + (uint32_t)(colg * 64) * BSTRIDE + boff;

    float d0[8][4], d1[8][4];
#pragma unroll
    for (int nt = 0; nt < 8; nt++)
#pragma unroll
        for (int e = 0; e < 4; e++) { d0[nt][e] = 0.f; d1[nt][e] = 0.f; }

    {
        loadB_async(base32, 0, 0, tid);
        asm volatile("cp.async.commit_group;" ::: "memory");
        float4 hv0 = make_float4(0.f, 0.f, 0.f, 0.f), hv1 = hv0;
        if (avalid) {
            hv0 = __ldg((const float4*)(harow + kq * 8));
            hv1 = __ldg((const float4*)(harow + kq * 8 + 4));
        }
        build_a_sts(sb, 0, 0, arow, kq, hv0, hv1, avalid, sa, smean, sinv, ln2s, ln2b);
        asm volatile("cp.async.wait_group 0;" ::: "memory");
        __syncthreads();
    }

    for (int kc = 0; kc < 8; kc++) {
        const int buf = kc & 1, nxt = buf ^ 1;
        float4 hv0 = make_float4(0.f, 0.f, 0.f, 0.f), hv1 = hv0;
        if (kc < 7) {
            loadB_async(base32, nxt, kc + 1, tid);
            asm volatile("cp.async.commit_group;" ::: "memory");
            if (avalid) {
                const float* hp = harow + (kc + 1) * 64 + kq * 8;
                hv0 = __ldg((const float4*)hp);
                hv1 = __ldg((const float4*)(hp + 4));
            }
        }

        {
            const uint32_t aB = aAddr + (uint32_t)(buf * A_BUF_STRIDE);
            const uint32_t bB = bAddr + (uint32_t)(buf * B_BUF_STRIDE);
#pragma unroll
            for (int ks = 0; ks < 4; ks++) {
                const uint32_t ka = aB + ks * 32;
                uint32_t ah[8];
                ldsm4(ah[0], ah[1], ah[2], ah[3], ka);
                ldsm4(ah[4], ah[5], ah[6], ah[7], ka + 16 * BSTRIDE);
                const uint32_t kb = bB + ks * 32;
#pragma unroll
                for (int np = 0; np < 4; np++) {
                    uint32_t bh[4];
                    const uint32_t bt = kb + (uint32_t)(np * 16 * BSTRIDE);
                    ldsm4(bh[0], bh[1], bh[2], bh[3], bt);
#pragma unroll
                    for (int hf = 0; hf < 2; hf++) {
                        const int nt = 2 * np + hf;
                        const uint32_t b0 = bh[2 * hf], b1 = bh[2 * hf + 1];
                        mma_f16(d0[nt][0], d0[nt][1], d0[nt][2], d0[nt][3],
                                ah[0], ah[1], ah[2], ah[3], b0, b1);
                        mma_f16(d1[nt][0], d1[nt][1], d1[nt][2], d1[nt][3],
                                ah[4], ah[5], ah[6], ah[7], b0, b1);
                    }
                }
            }
        }

        if (kc < 7)
            build_a_sts(sb, nxt, kc + 1, arow, kq, hv0, hv1, avalid, sa, smean, sinv, ln2s, ln2b);
        asm volatile("cp.async.wait_group 0;" ::: "memory");
        __syncthreads();
    }

    // ---------- stage D to smem ---------------------------------------------
    {
#pragma unroll
        for (int nt = 0; nt < 8; nt++) {
            const int c0 = colg * 64 + nt * 8 + 2 * tig;
            const int ra = rowg * 32 + g;
            *(float2*)(sd + (size_t)ra * 520 + c0)        = make_float2(d0[nt][0], d0[nt][1]);
            *(float2*)(sd + (size_t)(ra + 8) * 520 + c0)  = make_float2(d0[nt][2], d0[nt][3]);
            *(float2*)(sd + (size_t)(ra + 16) * 520 + c0) = make_float2(d1[nt][0], d1[nt][1]);
            *(float2*)(sd + (size_t)(ra + 24) * 520 + c0) = make_float2(d1[nt][2], d1[nt][3]);
        }
    }
    __syncthreads();

    // ---------- epilogue: y = h2n + silu(D + bm), LN3, write -----------------
    {
        const int prow = tid >> 3, cs = tid & 7;
        const int row = row0 + prow;
        const bool pv = (row < n);
        const float mean2 = smean[prow], inv2 = sinv[prow];
        float ar[4] = {sa[prow * 4 + 0], sa[prow * 4 + 1],
                       sa[prow * 4 + 2], sa[prow * 4 + 3]};
        float y[16][4];
        float s = 0.f, sq = 0.f;
        if (pv) {
            const float* hr = h + (size_t)row * 512;
#pragma unroll
            for (int j = 0; j < 16; j++) {
                const int c = cs * 4 + 32 * j;
                const float ah = ar[c >> 7];
                float4 hvv = __ldg((const float4*)(hr + c));
                float4 dv = *(const float4*)(sd + (size_t)prow * 520 + c);
                float4 vv = __ldg((const float4*)(g_vals + c));
                float4 s2 = __ldg((const float4*)(ln2s + c));
                float4 b2 = __ldg((const float4*)(ln2b + c));
                float4 bmv = __ldg((const float4*)(bm + c));
                float hx[4] = {hvv.x, hvv.y, hvv.z, hvv.w};
                float dx[4] = {dv.x, dv.y, dv.z, dv.w};
                float vx[4] = {vv.x, vv.y, vv.z, vv.w};
                float sx[4] = {s2.x, s2.y, s2.z, s2.w};
                float bx[4] = {b2.x, b2.y, b2.z, b2.w};
                float mx[4] = {bmv.x, bmv.y, bmv.z, bmv.w};
#pragma unroll
                for (int e = 0; e < 4; e++) {
                    float h2n = (hx[e] + ah * vx[e] - mean2) * inv2 * sx[e] + bx[e];
                    float yv = h2n + silu_fast(dx[e] + mx[e]);
                    y[j][e] = yv;
                    s += yv; sq += yv * yv;
                }
            }
        }
        s  += __shfl_xor_sync(FULL_MASK, s, 1);
        s  += __shfl_xor_sync(FULL_MASK, s, 2);
        s  += __shfl_xor_sync(FULL_MASK, s, 4);
        sq += __shfl_xor_sync(FULL_MASK, sq, 1);
        sq += __shfl_xor_sync(FULL_MASK, sq, 2);
        sq += __shfl_xor_sync(FULL_MASK, sq, 4);
        if (pv) {
            float mean = s * (1.f / 512.f);
            float var = sq * (1.f / 512.f) - mean * mean;
            float inv = rsqrtf(var + 1e-6f);
            float* orow = out + (size_t)row * 512;
#pragma unroll
            for (int j = 0; j < 16; j++) {
                const int c = cs * 4 + 32 * j;
                float4 sc = __ldg((const float4*)(ln3s + c));
                float4 bc = __ldg((const float4*)(ln3b + c));
                float4 o;
                o.x = (y[j][0] - mean) * inv * sc.x + bc.x;
                o.y = (y[j][1] - mean) * inv * sc.y + bc.y;
                o.z = (y[j][2] - mean) * inv * sc.z + bc.z;
                o.w = (y[j][3] - mean) * inv * sc.w + bc.w;
                *(float4*)(orow + c) = o;
            }
        }
    }
}

// ------------------------- host launch --------------------------------------
extern "C" void kernel_launch(void* const* d_in, const int* in_sizes, int n_in,
                              void* d_out, int out_size) {
    const float* h    = (const float*)d_in[0];
    const float* rk   = (const float*)d_in[2];
    const float* Wq   = (const float*)d_in[3];
    const float* bq   = (const float*)d_in[4];
    const float* Wv   = (const float*)d_in[5];
    const float* bv   = (const float*)d_in[6];
    const float* lrs  = (const float*)d_in[7];
    const float* lrb  = (const float*)d_in[8];
    const float* l1s  = (const float*)d_in[9];
    const float* l1b  = (const float*)d_in[10];
    const float* W1   = (const float*)d_in[11];
    const float* b1   = (const float*)d_in[12];
    const float* W2   = (const float*)d_in[13];
    const float* b2   = (const float*)d_in[14];
    const float* W3   = (const float*)d_in[15];
    const float* b3   = (const float*)d_in[16];
    const float* Wk   = (const float*)d_in[17];
    const float* bk   = (const float*)d_in[18];
    const float* ln2s = (const float*)d_in[19];
    const float* ln2b = (const float*)d_in[20];
    const float* Wm   = (const float*)d_in[21];
    const float* bm   = (const float*)d_in[22];
    const float* ln3s = (const float*)d_in[23];
    const float* ln3b = (const float*)d_in[24];
    float* out = (float*)d_out;

    const int n = in_sizes[0] / 512;
    const int nb1 = (n + 127) / 128;
    const int nbm = (n + 63) / 64;

    cudaFuncSetAttribute(k_main_mma, cudaFuncAttributeMaxDynamicSharedMemorySize, SMEM_DYN);

    k_prepF<<<dim3(17, 16), dim3(32, 32)>>>(Wm, Wq, bq, rk);
    k_pass1<<<nb1, 512>>>(h, n);
    k_redS<<<dim3(4, 16), 512>>>(nb1);
    k_smallA<<<1, 512>>>(nb1, Wv, bv, lrs, lrb, l1s, l1b, W1, b1);
    k_smallB2<<<8, 512>>>(W2, b2);
    k_smallC2<<<16, 512>>>(W3, b3);
    k_smallD2<<<9, 512>>>(Wk, bk);
    k_main_mma<<<nbm, 512, SMEM_DYN>>>(h, ln2s, ln2b, bm, ln3s, ln3b, out, n);
}

// round 14
// speedup vs baseline: 1.0450x; 1.0450x over previous
#include <cuda_runtime.h>
#include <cuda_bf16.h>
#include <cuda_fp16.h>
#include <cstdint>

#define FULL_MASK 0xFFFFFFFFu

// ------------------------- device scratch ----------------------------------
__device__ float g_u[512 * 4];
__device__ float g_c1[4];
__device__ float g_dpart[2048 * 4];
__device__ float g_spart[1024 * 2048];
__device__ float g_spart2[16 * 2048];
__device__ float g_x1[512];
__device__ float g_x2[512];
__device__ float g_qk[1024];
__device__ float g_U[512 * 4];
__device__ float g_c[4];
__device__ float g_vals[512];
__device__ float g_sv[4];
__device__ float g_svv[4];
// Wm^T in fp16, chunk-major: [kchunk64][n][kk]
__device__ __half g_WmB[512 * 512];

// ------------------------- helpers -----------------------------------------
__device__ __forceinline__ unsigned long long pack2(float lo, float hi) {
    unsigned long long r;
    asm("mov.b64 %0, {%1, %2};" : "=l"(r) : "f"(lo), "f"(hi));
    return r;
}
__device__ __forceinline__ void unpack2(unsigned long long v, float& lo, float& hi) {
    asm("mov.b64 {%0, %1}, %2;" : "=f"(lo), "=f"(hi) : "l"(v));
}
__device__ __forceinline__ void fma2(unsigned long long& acc,
                                     unsigned long long a, unsigned long long b) {
    asm("fma.rn.f32x2 %0, %1, %2, %0;" : "+l"(acc) : "l"(a), "l"(b));
}
__device__ __forceinline__ float silu_fast(float x) {
    return __fdividef(x, 1.0f + __expf(-x));
}
__device__ __forceinline__ uint32_t smem_u32(const void* p) {
    uint32_t a;
    asm("{ .reg .u64 t; cvta.to.shared.u64 t, %1; cvt.u32.u64 %0, t; }" : "=r"(a) : "l"(p));
    return a;
}
__device__ __forceinline__ uint32_t pkh(__half a, __half b) {
    return (uint32_t)__half_as_ushort(a) | ((uint32_t)__half_as_ushort(b) << 16);
}
__device__ __forceinline__ void cp16(uint32_t dst, const void* src) {
    asm volatile("cp.async.cg.shared.global [%0], [%1], 16;" :: "r"(dst), "l"(src));
}
__device__ __forceinline__ void ldsm4(uint32_t& r0, uint32_t& r1, uint32_t& r2,
                                      uint32_t& r3, uint32_t addr) {
    asm volatile("ldmatrix.sync.aligned.m8n8.x4.shared.b16 {%0,%1,%2,%3}, [%4];"
                 : "=r"(r0), "=r"(r1), "=r"(r2), "=r"(r3) : "r"(addr));
}
__device__ __forceinline__ void mma_f16(float& d0, float& d1, float& d2, float& d3,
                                        uint32_t a0, uint32_t a1, uint32_t a2, uint32_t a3,
                                        uint32_t b0, uint32_t b1) {
    asm volatile(
        "mma.sync.aligned.m16n8k16.row.col.f32.f16.f16.f32 "
        "{%0,%1,%2,%3}, {%4,%5,%6,%7}, {%8,%9}, {%0,%1,%2,%3};"
        : "+f"(d0), "+f"(d1), "+f"(d2), "+f"(d3)
        : "r"(a0), "r"(a1), "r"(a2), "r"(a3), "r"(b0), "r"(b1));
}

// ------------------------- kernel: prep fused (Wm fp16 + Wq/rk fold) --------
__global__ void __launch_bounds__(1024) k_prepF(const float* __restrict__ Wm,
                                                const float* __restrict__ Wq,
                                                const float* __restrict__ bq,
                                                const float* __restrict__ rk) {
    if (blockIdx.x == 16) {
        if (blockIdx.y == 0) {
            int t = threadIdx.y * 32 + threadIdx.x;
            if (t < 512) {
                float u[4];
#pragma unroll
                for (int r = 0; r < 4; r++) {
                    float s = 0.f;
#pragma unroll
                    for (int d = 0; d < 4; d++) s += Wq[t * 16 + 4 * r + d] * rk[4 * r + d];
                    u[r] = s;
                }
                ((float4*)g_u)[t] = make_float4(u[0], u[1], u[2], u[3]);
                if (t < 4) {
                    float s = 0.f;
#pragma unroll
                    for (int d = 0; d < 4; d++) s += bq[4 * t + d] * rk[4 * t + d];
                    g_c1[t] = s;
                }
            }
        }
        return;
    }
    __shared__ float tile[32][33];
    int tx = threadIdx.x, ty = threadIdx.y;
    tile[ty][tx] = Wm[(blockIdx.y * 32 + ty) * 512 + blockIdx.x * 32 + tx];
    __syncthreads();
    int n = blockIdx.x * 32 + ty;
    int k = blockIdx.y * 32 + tx;
    float v = tile[tx][ty];
    size_t idx = ((size_t)(k >> 6) * 512 + n) * 64 + (k & 63);
    g_WmB[idx] = __float2half(v);
}

// ------------------------- kernel: fused pass 1 -----------------------------
__global__ void __launch_bounds__(512) k_pass1(const float* __restrict__ h, int n) {
    __shared__ float4 se[128];
    __shared__ float sD[16][4];
    const int tid = threadIdx.x, warp = tid >> 5, lane = tid & 31;
    const int base = blockIdx.x * 128;

    const float c10 = g_c1[0], c11 = g_c1[1], c12 = g_c1[2], c13 = g_c1[3];
    float d0 = 0.f, d1 = 0.f, d2 = 0.f, d3 = 0.f;

#pragma unroll
    for (int rr = 0; rr < 8; rr++) {
        const int rloc = warp * 8 + rr;
        const int row = base + rloc;
        const bool valid = (row < n);
        const float* hr = h + (size_t)row * 512;

        float l0 = 0.f, l1 = 0.f, l2 = 0.f, l3 = 0.f;
        if (valid) {
#pragma unroll
            for (int t = 0; t < 16; t++) {
                int k = lane + 32 * t;
                float hk = __ldg(hr + k);
                float4 u = __ldg((const float4*)g_u + k);
                l0 += hk * u.x; l1 += hk * u.y; l2 += hk * u.z; l3 += hk * u.w;
            }
        }
#pragma unroll
        for (int o = 16; o; o >>= 1) {
            l0 += __shfl_xor_sync(FULL_MASK, l0, o);
            l1 += __shfl_xor_sync(FULL_MASK, l1, o);
            l2 += __shfl_xor_sync(FULL_MASK, l2, o);
            l3 += __shfl_xor_sync(FULL_MASK, l3, o);
        }
        if (lane == 0) {
            float m = valid ? 1.f : 0.f;
            float e0 = m * __expf(0.5f * (l0 + c10));
            float e1 = m * __expf(0.5f * (l1 + c11));
            float e2 = m * __expf(0.5f * (l2 + c12));
            float e3 = m * __expf(0.5f * (l3 + c13));
            se[rloc] = make_float4(e0, e1, e2, e3);
            d0 += e0; d1 += e1; d2 += e2; d3 += e3;
        }
    }
    if (lane == 0) {
        sD[warp][0] = d0; sD[warp][1] = d1; sD[warp][2] = d2; sD[warp][3] = d3;
    }
    __syncthreads();
    if (warp == 0 && lane < 4) {
        float s = 0.f;
#pragma unroll
        for (int w = 0; w < 16; w++) s += sD[w][lane];
        g_dpart[blockIdx.x * 4 + lane] = s;
    }

    const int c = tid;
    int lim = n - base; if (lim > 128) lim = 128;
    unsigned long long a01 = pack2(0.f, 0.f), a23 = pack2(0.f, 0.f);
    const float* hc = h + (size_t)base * 512 + c;
#pragma unroll 4
    for (int i = 0; i < lim; i++) {
        float4 e = se[i];
        float hv = __ldg(hc + (size_t)i * 512);
        unsigned long long hd = pack2(hv, hv);
        fma2(a01, hd, pack2(e.x, e.y));
        fma2(a23, hd, pack2(e.z, e.w));
    }
    float s0, s1, s2, s3;
    unpack2(a01, s0, s1);
    unpack2(a23, s2, s3);
    float* dst = g_spart + (size_t)blockIdx.x * 2048;
    dst[0 * 512 + c] = s0;
    dst[1 * 512 + c] = s1;
    dst[2 * 512 + c] = s2;
    dst[3 * 512 + c] = s3;
}

// ------------------------- kernel: S partial reduction (grid 4x16) ----------
__global__ void __launch_bounds__(512) k_redS(int nb) {
    const int col = blockIdx.x * 512 + threadIdx.x;
    const int chunk = (nb + 15) / 16;
    int i0 = blockIdx.y * chunk;
    int i1 = i0 + chunk; if (i1 > nb) i1 = nb;
    float s = 0.f;
    const float* src = g_spart + col;
#pragma unroll 4
    for (int i = i0; i < i1; i++) s += src[(size_t)i * 2048];
    g_spart2[blockIdx.y * 2048 + col] = s;
}

// ------------------------- kernel: smallA (S/D finalize, LN chain, x1) ------
__global__ void __launch_bounds__(512) k_smallA(int nb,
        const float* __restrict__ Wv,  const float* __restrict__ bv,
        const float* __restrict__ lrs, const float* __restrict__ lrb,
        const float* __restrict__ l1s, const float* __restrict__ l1b,
        const float* __restrict__ W1,  const float* __restrict__ b1) {
    __shared__ float sS[4 * 512];
    __shared__ float sDv[4];
    __shared__ float sNum[16];
    __shared__ float sr16[16];
    const int tid = threadIdx.x, warp = tid >> 5, lane = tid & 31;

#pragma unroll
    for (int r = 0; r < 4; r++) {
        int col = r * 512 + tid;
        float s = 0.f;
#pragma unroll
        for (int j = 0; j < 16; j++) s += g_spart2[j * 2048 + col];
        sS[col] = s;
    }
    if (warp < 4) {
        float s = 0.f;
        for (int i = lane; i < nb; i += 32) s += g_dpart[i * 4 + warp];
#pragma unroll
        for (int o = 16; o; o >>= 1) s += __shfl_xor_sync(FULL_MASK, s, o);
        if (lane == 0) sDv[warp] = s;
    }
    __syncthreads();

    {
        const int r = warp >> 2;
        float s = 0.f;
        for (int c = lane; c < 512; c += 32) s += sS[r * 512 + c] * Wv[c * 16 + warp];
#pragma unroll
        for (int o = 16; o; o >>= 1) s += __shfl_xor_sync(FULL_MASK, s, o);
        if (lane == 0) sNum[warp] = s;
    }
    __syncthreads();

    if (tid == 0) {
        float reg[16];
#pragma unroll
        for (int i = 0; i < 16; i++) reg[i] = sNum[i] / sDv[i >> 2] + bv[i];
#pragma unroll
        for (int pass = 0; pass < 2; pass++) {
            const float* sc = pass ? l1s : lrs;
            const float* bc = pass ? l1b : lrb;
            float m = 0.f;
            for (int i = 0; i < 16; i++) m += reg[i];
            m *= (1.f / 16.f);
            float v = 0.f;
            for (int i = 0; i < 16; i++) { float d = reg[i] - m; v += d * d; }
            v *= (1.f / 16.f);
            float inv = rsqrtf(v + 1e-6f);
            for (int i = 0; i < 16; i++) reg[i] = (reg[i] - m) * inv * sc[i] + bc[i];
        }
        for (int i = 0; i < 16; i++) sr16[i] = reg[i];
    }
    __syncthreads();

    float s = b1[tid];
#pragma unroll
    for (int i = 0; i < 16; i++) s += sr16[i] * W1[i * 512 + tid];
    g_x1[tid] = s / (1.f + expf(-s));
}

// ------------------------- kernel: smallB2 — x2 (grid 8) --------------------
__global__ void __launch_bounds__(512) k_smallB2(const float* __restrict__ W2,
                                                 const float* __restrict__ b2) {
    __shared__ float sx1[512];
    __shared__ float red[512];
    const int t = threadIdx.x;
    sx1[t] = g_x1[t];
    __syncthreads();
    const int j = blockIdx.x * 64 + (t & 63);
    const int ks = t >> 6;
    float s = 0.f;
    const float* w = W2 + (size_t)(ks * 64) * 512 + j;
    const float* xs = sx1 + ks * 64;
#pragma unroll 16
    for (int k = 0; k < 64; k++) s += xs[k] * __ldg(w + (size_t)k * 512);
    red[t] = s;
    __syncthreads();
    if (t < 64) {
        float v = b2[blockIdx.x * 64 + t];
#pragma unroll
        for (int i = 0; i < 8; i++) v += red[i * 64 + t];
        g_x2[blockIdx.x * 64 + t] = v / (1.f + expf(-v));
    }
}

// ------------------------- kernel: smallC2 — qk (grid 16) -------------------
__global__ void __launch_bounds__(512) k_smallC2(const float* __restrict__ W3,
                                                 const float* __restrict__ b3) {
    __shared__ float sx2[512];
    __shared__ float red[512];
    const int t = threadIdx.x;
    sx2[t] = g_x2[t];
    __syncthreads();
    const int j = blockIdx.x * 64 + (t & 63);
    const int ks = t >> 6;
    float s = 0.f;
    const float* w = W3 + (size_t)(ks * 64) * 1024 + j;
    const float* xs = sx2 + ks * 64;
#pragma unroll 16
    for (int k = 0; k < 64; k++) s += xs[k] * __ldg(w + (size_t)k * 1024);
    red[t] = s;
    __syncthreads();
    if (t < 64) {
        float v = b3[blockIdx.x * 64 + t];
#pragma unroll
        for (int i = 0; i < 8; i++) v += red[i * 64 + t];
        g_qk[blockIdx.x * 64 + t] = v;
    }
}

// ------------------------- kernel: smallD2 — U fold + stats (grid 9) --------
__global__ void __launch_bounds__(512) k_smallD2(const float* __restrict__ Wk,
                                                 const float* __restrict__ bk) {
    const int t = threadIdx.x, warp = t >> 5, lane = t & 31;
    if (blockIdx.x == 8) {
        g_vals[t] = g_qk[512 + t];
        if (warp < 4) {
            float s = 0.f, sv = 0.f, svv = 0.f;
            for (int d = lane; d < 128; d += 32) {
                float qv = g_qk[warp * 128 + d];
                s += bk[warp * 128 + d] * qv;
                float v = g_qk[512 + warp * 128 + d];
                sv += v; svv += v * v;
            }
#pragma unroll
            for (int o = 16; o; o >>= 1) {
                s   += __shfl_xor_sync(FULL_MASK, s, o);
                sv  += __shfl_xor_sync(FULL_MASK, sv, o);
                svv += __shfl_xor_sync(FULL_MASK, svv, o);
            }
            if (lane == 0) {
                g_c[warp] = s * rsqrtf(128.f);
                g_sv[warp] = sv;
                g_svv[warp] = svv;
            }
        }
        return;
    }
    __shared__ float sqk[1024];
    __shared__ float red[512];
    sqk[t] = g_qk[t];
    sqk[t + 512] = g_qk[t + 512];
    __syncthreads();
    const int r = blockIdx.x * 64 + (t >> 3);
    const int p = t & 7, head = p >> 1, half = p & 1;
    const float4* wr = (const float4*)(Wk + (size_t)r * 512 + head * 128 + half * 64);
    const float* qv = sqk + head * 128 + half * 64;
    float s = 0.f;
#pragma unroll
    for (int d4 = 0; d4 < 16; d4++) {
        float4 w = __ldg(wr + d4);
        s += w.x * qv[4 * d4 + 0] + w.y * qv[4 * d4 + 1]
           + w.z * qv[4 * d4 + 2] + w.w * qv[4 * d4 + 3];
    }
    red[t] = s;
    __syncthreads();
    if (t < 256) {
        const int rr = t >> 2, hh = t & 3;
        float v = red[rr * 8 + hh * 2] + red[rr * 8 + hh * 2 + 1];
        g_U[(blockIdx.x * 64 + rr) * 4 + hh] = v * rsqrtf(128.f);
    }
}

// ------------------------- kernel: main (HMMA fp16, whole-K A tile) ---------
// Block: 64 rows x 512 cols, 512 threads (16 warps, warp tile 32x64).
// A (h2n fp16, full K=512) built once in smem after Phase A; mainloop is
// pure B-load + MMA over 8 chunks of Kc=64. Epilogue reads h2n from A tile.
#define BSTRIDE 144
#define B_BUF_STRIDE 73728
#define ASTRIDE 1040
#define OFF_A 147456
#define OFF_SA 214016
#define OFF_MEAN 215040
#define OFF_INV 215296
#define SMEM_DYN 215552

__device__ __forceinline__ void loadB_async(uint32_t base32, int buf, int kc, int tid) {
    const __half* sH = g_WmB + (size_t)kc * 32768;
    uint32_t bh = base32 + buf * B_BUF_STRIDE;
#pragma unroll
    for (int j = 0; j < 8; j++) {
        int f = j * 512 + tid;
        uint32_t doff = (uint32_t)((f >> 3) * BSTRIDE + (f & 7) * 16);
        cp16(bh + doff, sH + f * 8);
    }
}

__global__ void __launch_bounds__(512, 1) k_main_mma(const float* __restrict__ h,
        const float* __restrict__ ln2s, const float* __restrict__ ln2b,
        const float* __restrict__ bm,
        const float* __restrict__ ln3s, const float* __restrict__ ln3b,
        float* __restrict__ out, int n) {
    extern __shared__ char sb[];
    const uint32_t base32 = smem_u32(sb);
    float* sa    = (float*)(sb + OFF_SA);
    float* smean = (float*)(sb + OFF_MEAN);
    float* sinv  = (float*)(sb + OFF_INV);
    float* sd    = (float*)sb;

    const int tid = threadIdx.x, warp = tid >> 5, lane = tid & 31;
    const int row0 = blockIdx.x * 64;

    // ---------- Phase A: per-row softmax + closed-form LN2 stats ------------
    {
        const float c0 = g_c[0], c1 = g_c[1], c2 = g_c[2], c3 = g_c[3];
        const float sv0 = g_sv[0], sv1 = g_sv[1], sv2 = g_sv[2], sv3 = g_sv[3];
        const float w0 = g_svv[0], w1 = g_svv[1], w2 = g_svv[2], w3 = g_svv[3];
#pragma unroll
        for (int rr = 0; rr < 4; rr++) {
            const int rloc = warp * 4 + rr;
            const int row = row0 + rloc;
            const bool valid = (row < n);
            const float* hr = h + (size_t)row * 512;
            float l0 = 0.f, l1 = 0.f, l2 = 0.f, l3 = 0.f;
            float hv0 = 0.f, hv1 = 0.f, hv2 = 0.f, hv3 = 0.f;
            float sh = 0.f, sq = 0.f;
            if (valid) {
#pragma unroll
                for (int t = 0; t < 16; t++) {
                    int k = lane + 32 * t;
                    float hk = __ldg(hr + k);
                    float4 u = __ldg((const float4*)g_U + k);
                    float vk = __ldg(g_vals + k);
                    l0 += hk * u.x; l1 += hk * u.y; l2 += hk * u.z; l3 += hk * u.w;
                    float p = hk * vk;
                    if (t < 4) hv0 += p; else if (t < 8) hv1 += p;
                    else if (t < 12) hv2 += p; else hv3 += p;
                    sh += hk; sq += hk * hk;
                }
            }
#pragma unroll
            for (int o = 16; o; o >>= 1) {
                l0 += __shfl_xor_sync(FULL_MASK, l0, o);
                l1 += __shfl_xor_sync(FULL_MASK, l1, o);
                l2 += __shfl_xor_sync(FULL_MASK, l2, o);
                l3 += __shfl_xor_sync(FULL_MASK, l3, o);
                hv0 += __shfl_xor_sync(FULL_MASK, hv0, o);
                hv1 += __shfl_xor_sync(FULL_MASK, hv1, o);
                hv2 += __shfl_xor_sync(FULL_MASK, hv2, o);
                hv3 += __shfl_xor_sync(FULL_MASK, hv3, o);
                sh += __shfl_xor_sync(FULL_MASK, sh, o);
                sq += __shfl_xor_sync(FULL_MASK, sq, o);
            }
            if (lane == 0) {
                if (valid) {
                    l0 += c0; l1 += c1; l2 += c2; l3 += c3;
                    float mx = fmaxf(fmaxf(l0, l1), fmaxf(l2, l3));
                    float e0 = __expf(l0 - mx), e1 = __expf(l1 - mx);
                    float e2 = __expf(l2 - mx), e3 = __expf(l3 - mx);
                    float si = __fdividef(1.f, e0 + e1 + e2 + e3);
                    float a0 = e0 * si, a1 = e1 * si, a2 = e2 * si, a3 = e3 * si;
                    float sum = sh + a0 * sv0 + a1 * sv1 + a2 * sv2 + a3 * sv3;
                    float ssq = sq + 2.f * (a0 * hv0 + a1 * hv1 + a2 * hv2 + a3 * hv3)
                              + a0 * a0 * w0 + a1 * a1 * w1 + a2 * a2 * w2 + a3 * a3 * w3;
                    float mean = sum * (1.f / 512.f);
                    float var = ssq * (1.f / 512.f) - mean * mean;
                    sa[rloc * 4 + 0] = a0; sa[rloc * 4 + 1] = a1;
                    sa[rloc * 4 + 2] = a2; sa[rloc * 4 + 3] = a3;
                    smean[rloc] = mean;
                    sinv[rloc] = rsqrtf(var + 1e-6f);
                } else {
                    sa[rloc * 4 + 0] = 0.f; sa[rloc * 4 + 1] = 0.f;
                    sa[rloc * 4 + 2] = 0.f; sa[rloc * 4 + 3] = 0.f;
                    smean[rloc] = 0.f; sinv[rloc] = 0.f;
                }
            }
        }
    }
    __syncthreads();

    // ---------- Build full A tile (h2n fp16, K=512) --------------------------
    {
        const int arow = tid >> 3, kq = tid & 7;
        const bool avalid = (row0 + arow < n);
        const float* harow = h + (size_t)(row0 + arow) * 512;
        const float mean = smean[arow], inv = sinv[arow];
        char* arb = sb + OFF_A + arow * ASTRIDE;
#pragma unroll
        for (int kc = 0; kc < 8; kc++) {
            const int kg = kc * 64 + kq * 8;
            const float ah = sa[arow * 4 + (kc >> 1)];
            float4 hv0 = make_float4(0.f, 0.f, 0.f, 0.f), hv1 = hv0;
            if (avalid) {
                hv0 = __ldg((const float4*)(harow + kg));
                hv1 = __ldg((const float4*)(harow + kg + 4));
            }
            float4 vA = __ldg((const float4*)(g_vals + kg));
            float4 vB = __ldg((const float4*)(g_vals + kg + 4));
            float4 sA = __ldg((const float4*)(ln2s + kg));
            float4 sB = __ldg((const float4*)(ln2s + kg + 4));
            float4 bA = __ldg((const float4*)(ln2b + kg));
            float4 bB = __ldg((const float4*)(ln2b + kg + 4));
            float hx[8] = {hv0.x, hv0.y, hv0.z, hv0.w, hv1.x, hv1.y, hv1.z, hv1.w};
            float vx[8] = {vA.x, vA.y, vA.z, vA.w, vB.x, vB.y, vB.z, vB.w};
            float sx[8] = {sA.x, sA.y, sA.z, sA.w, sB.x, sB.y, sB.z, sB.w};
            float bx[8] = {bA.x, bA.y, bA.z, bA.w, bB.x, bB.y, bB.z, bB.w};
            uint32_t w[4];
#pragma unroll
            for (int p = 0; p < 4; p++) {
                float x0 = avalid ? ((hx[2 * p] + ah * vx[2 * p] - mean) * inv * sx[2 * p] + bx[2 * p]) : 0.f;
                float x1 = avalid ? ((hx[2 * p + 1] + ah * vx[2 * p + 1] - mean) * inv * sx[2 * p + 1] + bx[2 * p + 1]) : 0.f;
                w[p] = pkh(__float2half(x0), __float2half(x1));
            }
            *(uint4*)(arb + kc * 128 + kq * 16) = make_uint4(w[0], w[1], w[2], w[3]);
        }
    }

    // ---------- GEMM pipeline (8 chunks of Kc=64, B-only double buffer) ------
    const int rowg = warp >> 3, colg = warp & 7;
    const int g = lane >> 2, tig = lane & 3;

    const uint32_t aoff = (uint32_t)((lane & 15) * ASTRIDE + (lane >> 4) * 16);
    const uint32_t boff = (uint32_t)(((((lane >> 4) << 3) + (lane & 7)) * BSTRIDE)
                                     + ((lane >> 3) & 1) * 16);
    const uint32_t aAddr = base32 + OFF_A + (uint32_t)(rowg * 32) * ASTRIDE + aoff;
    const uint32_t bAddr = base32 + (uint32_t)(colg * 64) * BSTRIDE + boff;

    float d0[8][4], d1[8][4];
#pragma unroll
    for (int nt = 0; nt < 8; nt++)
#pragma unroll
        for (int e = 0; e < 4; e++) { d0[nt][e] = 0.f; d1[nt][e] = 0.f; }

    loadB_async(base32, 0, 0, tid);
    asm volatile("cp.async.commit_group;" ::: "memory");
    asm volatile("cp.async.wait_group 0;" ::: "memory");
    __syncthreads();   // A tile + B chunk 0 ready

    for (int kc = 0; kc < 8; kc++) {
        const int buf = kc & 1, nxt = buf ^ 1;
        if (kc < 7) {
            loadB_async(base32, nxt, kc + 1, tid);
            asm volatile("cp.async.commit_group;" ::: "memory");
        }

        {
            const uint32_t aB = aAddr + (uint32_t)(kc * 128);
            const uint32_t bB = bAddr + (uint32_t)(buf * B_BUF_STRIDE);
#pragma unroll
            for (int ks = 0; ks < 4; ks++) {
                const uint32_t ka = aB + ks * 32;
                uint32_t ah[8];
                ldsm4(ah[0], ah[1], ah[2], ah[3], ka);
                ldsm4(ah[4], ah[5], ah[6], ah[7], ka + 16 * ASTRIDE);
                const uint32_t kb = bB + ks * 32;
#pragma unroll
                for (int np = 0; np < 4; np++) {
                    uint32_t bh[4];
                    const uint32_t bt = kb + (uint32_t)(np * 16 * BSTRIDE);
                    ldsm4(bh[0], bh[1], bh[2], bh[3], bt);
#pragma unroll
                    for (int hf = 0; hf < 2; hf++) {
                        const int nt = 2 * np + hf;
                        const uint32_t b0 = bh[2 * hf], b1 = bh[2 * hf + 1];
                        mma_f16(d0[nt][0], d0[nt][1], d0[nt][2], d0[nt][3],
                                ah[0], ah[1], ah[2], ah[3], b0, b1);
                        mma_f16(d1[nt][0], d1[nt][1], d1[nt][2], d1[nt][3],
                                ah[4], ah[5], ah[6], ah[7], b0, b1);
                    }
                }
            }
        }

        asm volatile("cp.async.wait_group 0;" ::: "memory");
        __syncthreads();
    }

    // ---------- stage D to smem (B region, now free) -------------------------
    {
#pragma unroll
        for (int nt = 0; nt < 8; nt++) {
            const int c0 = colg * 64 + nt * 8 + 2 * tig;
            const int ra = rowg * 32 + g;
            *(float2*)(sd + (size_t)ra * 520 + c0)        = make_float2(d0[nt][0], d0[nt][1]);
            *(float2*)(sd + (size_t)(ra + 8) * 520 + c0)  = make_float2(d0[nt][2], d0[nt][3]);
            *(float2*)(sd + (size_t)(ra + 16) * 520 + c0) = make_float2(d1[nt][0], d1[nt][1]);
            *(float2*)(sd + (size_t)(ra + 24) * 520 + c0) = make_float2(d1[nt][2], d1[nt][3]);
        }
    }
    __syncthreads();

    // ---------- epilogue: y = h2n(from A) + silu(D + bm), LN3, write ---------
    {
        const int prow = tid >> 3, cs = tid & 7;
        const int row = row0 + prow;
        const bool pv = (row < n);
        const char* arow_b = sb + OFF_A + prow * ASTRIDE;
        float y[16][4];
        float s = 0.f, sq = 0.f;
        if (pv) {
#pragma unroll
            for (int j = 0; j < 16; j++) {
                const int c = cs * 4 + 32 * j;
                uint2 ap = *(const uint2*)(arow_b + c * 2);
                float2 a01 = __half22float2(*(const __half2*)&ap.x);
                float2 a23 = __half22float2(*(const __half2*)&ap.y);
                float4 dv = *(const float4*)(sd + (size_t)prow * 520 + c);
                float4 bmv = __ldg((const float4*)(bm + c));
                float h2n[4] = {a01.x, a01.y, a23.x, a23.y};
                float dx[4] = {dv.x, dv.y, dv.z, dv.w};
                float mx[4] = {bmv.x, bmv.y, bmv.z, bmv.w};
#pragma unroll
                for (int e = 0; e < 4; e++) {
                    float yv = h2n[e] + silu_fast(dx[e] + mx[e]);
                    y[j][e] = yv;
                    s += yv; sq += yv * yv;
                }
            }
        }
        s  += __shfl_xor_sync(FULL_MASK, s, 1);
        s  += __shfl_xor_sync(FULL_MASK, s, 2);
        s  += __shfl_xor_sync(FULL_MASK, s, 4);
        sq += __shfl_xor_sync(FULL_MASK, sq, 1);
        sq += __shfl_xor_sync(FULL_MASK, sq, 2);
        sq += __shfl_xor_sync(FULL_MASK, sq, 4);
        if (pv) {
            float mean = s * (1.f / 512.f);
            float var = sq * (1.f / 512.f) - mean * mean;
            float inv = rsqrtf(var + 1e-6f);
            float* orow = out + (size_t)row * 512;
#pragma unroll
            for (int j = 0; j < 16; j++) {
                const int c = cs * 4 + 32 * j;
                float4 sc = __ldg((const float4*)(ln3s + c));
                float4 bc = __ldg((const float4*)(ln3b + c));
                float4 o;
                o.x = (y[j][0] - mean) * inv * sc.x + bc.x;
                o.y = (y[j][1] - mean) * inv * sc.y + bc.y;
                o.z = (y[j][2] - mean) * inv * sc.z + bc.z;
                o.w = (y[j][3] - mean) * inv * sc.w + bc.w;
                *(float4*)(orow + c) = o;
            }
        }
    }
}

// ------------------------- host launch --------------------------------------
extern "C" void kernel_launch(void* const* d_in, const int* in_sizes, int n_in,
                              void* d_out, int out_size) {
    const float* h    = (const float*)d_in[0];
    const float* rk   = (const float*)d_in[2];
    const float* Wq   = (const float*)d_in[3];
    const float* bq   = (const float*)d_in[4];
    const float* Wv   = (const float*)d_in[5];
    const float* bv   = (const float*)d_in[6];
    const float* lrs  = (const float*)d_in[7];
    const float* lrb  = (const float*)d_in[8];
    const float* l1s  = (const float*)d_in[9];
    const float* l1b  = (const float*)d_in[10];
    const float* W1   = (const float*)d_in[11];
    const float* b1   = (const float*)d_in[12];
    const float* W2   = (const float*)d_in[13];
    const float* b2   = (const float*)d_in[14];
    const float* W3   = (const float*)d_in[15];
    const float* b3   = (const float*)d_in[16];
    const float* Wk   = (const float*)d_in[17];
    const float* bk   = (const float*)d_in[18];
    const float* ln2s = (const float*)d_in[19];
    const float* ln2b = (const float*)d_in[20];
    const float* Wm   = (const float*)d_in[21];
    const float* bm   = (const float*)d_in[22];
    const float* ln3s = (const float*)d_in[23];
    const float* ln3b = (const float*)d_in[24];
    float* out = (float*)d_out;

    const int n = in_sizes[0] / 512;
    const int nb1 = (n + 127) / 128;
    const int nbm = (n + 63) / 64;

    cudaFuncSetAttribute(k_main_mma, cudaFuncAttributeMaxDynamicSharedMemorySize, SMEM_DYN);

    k_prepF<<<dim3(17, 16), dim3(32, 32)>>>(Wm, Wq, bq, rk);
    k_pass1<<<nb1, 512>>>(h, n);
    k_redS<<<dim3(4, 16), 512>>>(nb1);
    k_smallA<<<1, 512>>>(nb1, Wv, bv, lrs, lrb, l1s, l1b, W1, b1);
    k_smallB2<<<8, 512>>>(W2, b2);
    k_smallC2<<<16, 512>>>(W3, b3);
    k_smallD2<<<9, 512>>>(Wk, bk);
    k_main_mma<<<nbm, 512, SMEM_DYN>>>(h, ln2s, ln2b, bm, ln3s, ln3b, out, n);
}